// round 1
// baseline (speedup 1.0000x reference)
#include <cuda_runtime.h>
#include <math.h>

// Problem constants
#define BATCH 2
#define SEQ   2048
#define DIM   1024
#define HEADS 16
#define HD    64
#define MTOK  (BATCH * SEQ)            // 4096 tokens
#define HALF  (DIM / 2)                // 512

// Scratch (no cudaMalloc allowed -> __device__ globals)
__device__ float g_q[MTOK * DIM];
__device__ float g_k[MTOK * DIM];
__device__ float g_v[MTOK * DIM];
__device__ float g_x[MTOK * DIM];      // scrambled ctx for O-projection
__device__ float g_cos[SEQ * HALF];
__device__ float g_sin[SEQ * HALF];

// ---------------------------------------------------------------------------
// RoPE tables: cos/sin(s * invfreq[j]), j in [0,512). Double precision so our
// table error is negligible vs the reference's own fp32 rounding.
// ---------------------------------------------------------------------------
__global__ void rope_tables_kernel() {
    int idx = blockIdx.x * blockDim.x + threadIdx.x;
    if (idx >= SEQ * HALF) return;
    int s = idx >> 9;          // / 512
    int j = idx & (HALF - 1);  // % 512
    double inv = exp(-((double)(2 * j) / (double)DIM) * log(10000.0));
    double arg = (double)s * inv;
    g_cos[idx] = (float)cos(arg);
    g_sin[idx] = (float)sin(arg);
}

// ---------------------------------------------------------------------------
// fp32 SIMT GEMM: C[M,1024] = A[M,1024] @ W[1024,1024] + bias
// 128x128 block tile, TK=8, 256 threads, 8x8 per-thread microtile.
// ---------------------------------------------------------------------------
#define TM 128
#define TN 128
#define TK 8

__global__ __launch_bounds__(256, 2)
void gemm_kernel(const float* __restrict__ A, const float* __restrict__ W,
                 const float* __restrict__ bias, float* __restrict__ C) {
    const int K = DIM, N = DIM;
    __shared__ float As[TK][TM];
    __shared__ float Bs[TK][TN];

    int tid  = threadIdx.x;
    int row0 = blockIdx.y * TM;
    int col0 = blockIdx.x * TN;

    // A load: each thread one float4: m = tid/2, k4 = (tid&1)*4
    int am = tid >> 1;
    int ak = (tid & 1) * 4;
    // B load: each thread one float4: k = tid/32, n4 = (tid&31)*4
    int bk  = tid >> 5;
    int bn4 = (tid & 31) * 4;

    int tx = tid & 15;   // column group (8 cols)
    int ty = tid >> 4;   // row group (8 rows)

    float acc[8][8];
#pragma unroll
    for (int i = 0; i < 8; i++)
#pragma unroll
        for (int j = 0; j < 8; j++) acc[i][j] = 0.0f;

    const float* Aptr = A + (size_t)(row0 + am) * K + ak;
    const float* Wptr = W + (size_t)bk * N + col0 + bn4;

    for (int k0 = 0; k0 < K; k0 += TK) {
        float4 av = *(const float4*)(Aptr + k0);
        float4 bv = *(const float4*)(Wptr + (size_t)k0 * N);
        __syncthreads();
        As[ak + 0][am] = av.x;
        As[ak + 1][am] = av.y;
        As[ak + 2][am] = av.z;
        As[ak + 3][am] = av.w;
        *(float4*)&Bs[bk][bn4] = bv;
        __syncthreads();
#pragma unroll
        for (int kk = 0; kk < TK; kk++) {
            float a[8], b[8];
            *(float4*)(a)     = *(const float4*)&As[kk][ty * 8];
            *(float4*)(a + 4) = *(const float4*)&As[kk][ty * 8 + 4];
            *(float4*)(b)     = *(const float4*)&Bs[kk][tx * 8];
            *(float4*)(b + 4) = *(const float4*)&Bs[kk][tx * 8 + 4];
#pragma unroll
            for (int i = 0; i < 8; i++)
#pragma unroll
                for (int j = 0; j < 8; j++) acc[i][j] += a[i] * b[j];
        }
    }

    float breg[8];
#pragma unroll
    for (int j = 0; j < 8; j++) breg[j] = bias[col0 + tx * 8 + j];

#pragma unroll
    for (int i = 0; i < 8; i++) {
        int r = row0 + ty * 8 + i;
        float* dst = &C[(size_t)r * N + col0 + tx * 8];
        float4 o0, o1;
        o0.x = acc[i][0] + breg[0]; o0.y = acc[i][1] + breg[1];
        o0.z = acc[i][2] + breg[2]; o0.w = acc[i][3] + breg[3];
        o1.x = acc[i][4] + breg[4]; o1.y = acc[i][5] + breg[5];
        o1.z = acc[i][6] + breg[6]; o1.w = acc[i][7] + breg[7];
        *(float4*)(dst)     = o0;
        *(float4*)(dst + 4) = o1;
    }
}

// ---------------------------------------------------------------------------
// Per-token attention: RoPE(q,k) -> 16x16 scores -> softmax -> ctx -> scramble.
// One block per token (4096 blocks, 256 threads).
// Scramble: ctx[b,s,h,e] -> g_x[b, h*128 + s/16, (s%16)*64 + e]
// ---------------------------------------------------------------------------
__global__ __launch_bounds__(256)
void attn_kernel(float* __restrict__ attn_out, int write_attn) {
    __shared__ float q[DIM], k[DIM], v[DIM], qr[DIM], kr[DIM];
    __shared__ float sc[HEADS * HEADS];

    int t   = blockIdx.x;        // token index (b*S + s)
    int b   = t >> 11;           // / 2048
    int s   = t & (SEQ - 1);     // % 2048
    int tid = threadIdx.x;

    const float* qg = g_q + (size_t)t * DIM;
    const float* kg = g_k + (size_t)t * DIM;
    const float* vg = g_v + (size_t)t * DIM;

    for (int d = tid; d < DIM; d += 256) {
        q[d] = qg[d]; k[d] = kg[d]; v[d] = vg[d];
    }
    __syncthreads();

    // RoPE over full hidden dim
    for (int d = tid; d < DIM; d += 256) {
        int j = d & (HALF - 1);
        float c  = g_cos[s * HALF + j];
        float sn = g_sin[s * HALF + j];
        float rq = (d < HALF) ? -q[d + HALF] : q[d - HALF];
        float rk = (d < HALF) ? -k[d + HALF] : k[d - HALF];
        qr[d] = q[d] * c + rq * sn;
        kr[d] = k[d] * c + rk * sn;
    }
    __syncthreads();

    // scores[i][j] = dot(q_i, k_j) / sqrt(64), one thread per (i,j)
    {
        int i = tid >> 4, j = tid & 15;
        float sum = 0.0f;
        const float* qp = &qr[i * HD];
        const float* kp = &kr[j * HD];
#pragma unroll
        for (int e = 0; e < HD; e++) sum += qp[e] * kp[e];
        sc[tid] = sum * 0.125f;
    }
    __syncthreads();

    // softmax over j, one thread per row i
    if (tid < HEADS) {
        float m = -1e30f;
#pragma unroll
        for (int j = 0; j < HEADS; j++) m = fmaxf(m, sc[tid * HEADS + j]);
        float ev[HEADS];
        float ssum = 0.0f;
#pragma unroll
        for (int j = 0; j < HEADS; j++) {
            ev[j] = expf(sc[tid * HEADS + j] - m);
            ssum += ev[j];
        }
        float inv = 1.0f / ssum;
#pragma unroll
        for (int j = 0; j < HEADS; j++) sc[tid * HEADS + j] = ev[j] * inv;
    }
    __syncthreads();

    if (write_attn) {
        attn_out[(size_t)t * 256 + tid] = sc[tid];
    }

    // ctx[i][e] = sum_j attn[i][j] * v[j][e]; write scrambled
    for (int idx = tid; idx < DIM; idx += 256) {
        int i = idx >> 6;          // head
        int e = idx & (HD - 1);    // within-head
        float sum = 0.0f;
#pragma unroll
        for (int j = 0; j < HEADS; j++) sum += sc[i * HEADS + j] * v[j * HD + e];
        int r = i * (SEQ / HEADS) + (s >> 4);       // h*128 + s/16
        int c = ((s & 15) << 6) | e;                // (s%16)*64 + e
        g_x[(size_t)b * SEQ * DIM + (size_t)r * DIM + c] = sum;
    }
}

// ---------------------------------------------------------------------------
// Host launcher
// ---------------------------------------------------------------------------
extern "C" void kernel_launch(void* const* d_in, const int* in_sizes, int n_in,
                              void* d_out, int out_size) {
    const float* inputs  = (const float*)d_in[0];
    const float* context = (const float*)d_in[1];
    const float* Wq = (const float*)d_in[2];
    const float* bq = (const float*)d_in[3];
    const float* Wk = (const float*)d_in[4];
    const float* bk = (const float*)d_in[5];
    const float* Wv = (const float*)d_in[6];
    const float* bv = (const float*)d_in[7];
    const float* Wo = (const float*)d_in[8];
    const float* bo = (const float*)d_in[9];
    float* out = (float*)d_out;

    float *pq, *pk, *pv, *px;
    cudaGetSymbolAddress((void**)&pq, g_q);
    cudaGetSymbolAddress((void**)&pk, g_k);
    cudaGetSymbolAddress((void**)&pv, g_v);
    cudaGetSymbolAddress((void**)&px, g_x);

    const int out_elems  = MTOK * DIM;            // 4194304
    const int attn_elems = MTOK * HEADS * HEADS;  // 1048576
    int write_attn = (out_size >= out_elems + attn_elems) ? 1 : 0;
    float* attn_out = out + out_elems;

    // 1. RoPE tables
    {
        int n = SEQ * HALF;
        rope_tables_kernel<<<(n + 255) / 256, 256>>>();
    }

    dim3 ggrid(DIM / TN, MTOK / TM);  // (8, 32)

    // 2-4. Q/K/V projections
    gemm_kernel<<<ggrid, 256>>>(inputs,  Wq, bq, pq);
    gemm_kernel<<<ggrid, 256>>>(context, Wk, bk, pk);
    gemm_kernel<<<ggrid, 256>>>(context, Wv, bv, pv);

    // 5. RoPE + per-token head attention + scramble
    attn_kernel<<<MTOK, 256>>>(attn_out, write_attn);

    // 6. Output projection
    gemm_kernel<<<ggrid, 256>>>(px, Wo, bo, out);
}

// round 4
// speedup vs baseline: 2.7815x; 2.7815x over previous
#include <cuda_runtime.h>
#include <cuda_bf16.h>
#include <stdint.h>
#include <math.h>

// Problem constants
#define BATCH 2
#define SEQ   2048
#define DIM   1024
#define HEADS 16
#define HD    64
#define MTOK  (BATCH * SEQ)            // 4096 tokens
#define HALF  (DIM / 2)                // 512

// GEMM tiling
#define GM 128
#define GN 128
#define GKC 64                          // bf16 k-elems per chunk (128 bytes/row)
#define NCHUNK (DIM / GKC)              // 16
#define NSTAGE 3
#define STAGE_BYTES 65536
#define RA_HI 0
#define RA_LO 16384
#define RB_HI 32768
#define RB_LO 49152
#define SMEM_TOTAL (NSTAGE * STAGE_BYTES)   // 192 KB

// ---------------------------------------------------------------------------
// Device scratch (no cudaMalloc allowed)
// ---------------------------------------------------------------------------
__device__ float g_q[MTOK * DIM];
__device__ float g_k[MTOK * DIM];
__device__ float g_v[MTOK * DIM];
__device__ float g_cos[SEQ * HALF];
__device__ float g_sin[SEQ * HALF];
__device__ float g_invf[HALF];

__device__ __nv_bfloat16 g_in_hi[MTOK * DIM], g_in_lo[MTOK * DIM];
__device__ __nv_bfloat16 g_cx_hi[MTOK * DIM], g_cx_lo[MTOK * DIM];
__device__ __nv_bfloat16 g_xx_hi[MTOK * DIM], g_xx_lo[MTOK * DIM];
__device__ __nv_bfloat16 g_wq_hi[DIM * DIM], g_wq_lo[DIM * DIM];
__device__ __nv_bfloat16 g_wk_hi[DIM * DIM], g_wk_lo[DIM * DIM];
__device__ __nv_bfloat16 g_wv_hi[DIM * DIM], g_wv_lo[DIM * DIM];
__device__ __nv_bfloat16 g_wo_hi[DIM * DIM], g_wo_lo[DIM * DIM];

// ---------------------------------------------------------------------------
// Helpers
// ---------------------------------------------------------------------------
__device__ __forceinline__ uint32_t smem_u32(const void* p) {
    uint32_t a;
    asm("{ .reg .u64 t; cvta.to.shared.u64 t, %1; cvt.u32.u64 %0, t; }"
        : "=r"(a) : "l"(p));
    return a;
}

__device__ __forceinline__ void cp16(uint32_t smem, const void* g) {
    asm volatile("cp.async.cg.shared.global [%0], [%1], 16;" :: "r"(smem), "l"(g));
}
__device__ __forceinline__ void cp_commit() {
    asm volatile("cp.async.commit_group;" ::: "memory");
}
template <int N>
__device__ __forceinline__ void cp_wait() {
    asm volatile("cp.async.wait_group %0;" :: "n"(N) : "memory");
}

#define SWZ(off) ((uint32_t)(off) ^ ((((uint32_t)(off)) >> 3) & 0x70u))

__device__ __forceinline__ void ldsm_x4(uint32_t* r, uint32_t addr) {
    asm volatile("ldmatrix.sync.aligned.m8n8.x4.shared.b16 {%0,%1,%2,%3}, [%4];"
                 : "=r"(r[0]), "=r"(r[1]), "=r"(r[2]), "=r"(r[3]) : "r"(addr));
}

__device__ __forceinline__ void mma16816(float* d, const uint32_t* a,
                                         uint32_t b0, uint32_t b1) {
    asm volatile(
        "mma.sync.aligned.m16n8k16.row.col.f32.bf16.bf16.f32 "
        "{%0,%1,%2,%3}, {%4,%5,%6,%7}, {%8,%9}, {%0,%1,%2,%3};"
        : "+f"(d[0]), "+f"(d[1]), "+f"(d[2]), "+f"(d[3])
        : "r"(a[0]), "r"(a[1]), "r"(a[2]), "r"(a[3]), "r"(b0), "r"(b1));
}

// ---------------------------------------------------------------------------
// RoPE tables
// ---------------------------------------------------------------------------
__global__ void rope_inv_kernel() {
    int j = threadIdx.x;
    if (j < HALF) {
        double inv = exp(-((double)(2 * j) / (double)DIM) * log(10000.0));
        g_invf[j] = (float)inv;
    }
}

__global__ void rope_tab_kernel() {
    int idx = blockIdx.x * 256 + threadIdx.x;
    int s = idx >> 9;
    int j = idx & (HALF - 1);
    float arg = (float)s * g_invf[j];
    float sn, cs;
    sincosf(arg, &sn, &cs);
    g_cos[idx] = cs;
    g_sin[idx] = sn;
}

// ---------------------------------------------------------------------------
// fp32 -> bf16 hi/lo split (elementwise, same layout)
// ---------------------------------------------------------------------------
__global__ void convert_act_kernel(const float* __restrict__ X,
                                   __nv_bfloat16* __restrict__ hi,
                                   __nv_bfloat16* __restrict__ lo) {
    int i = (blockIdx.x * 256 + threadIdx.x) * 4;
    float4 x = *(const float4*)(X + i);
    __nv_bfloat16 h0 = __float2bfloat16(x.x);
    __nv_bfloat16 h1 = __float2bfloat16(x.y);
    __nv_bfloat16 h2 = __float2bfloat16(x.z);
    __nv_bfloat16 h3 = __float2bfloat16(x.w);
    *(__nv_bfloat162*)(hi + i)     = __halves2bfloat162(h0, h1);
    *(__nv_bfloat162*)(hi + i + 2) = __halves2bfloat162(h2, h3);
    __nv_bfloat16 l0 = __float2bfloat16(x.x - __bfloat162float(h0));
    __nv_bfloat16 l1 = __float2bfloat16(x.y - __bfloat162float(h1));
    __nv_bfloat16 l2 = __float2bfloat16(x.z - __bfloat162float(h2));
    __nv_bfloat16 l3 = __float2bfloat16(x.w - __bfloat162float(h3));
    *(__nv_bfloat162*)(lo + i)     = __halves2bfloat162(l0, l1);
    *(__nv_bfloat162*)(lo + i + 2) = __halves2bfloat162(l2, l3);
}

// ---------------------------------------------------------------------------
// W [K][N] fp32 -> transposed hi/lo bf16 [N][K]
// ---------------------------------------------------------------------------
__global__ void convert_w_kernel(const float* __restrict__ W,
                                 __nv_bfloat16* __restrict__ hi,
                                 __nv_bfloat16* __restrict__ lo) {
    __shared__ float t[32][33];
    int k0 = blockIdx.y * 32, n0 = blockIdx.x * 32;
    int tx = threadIdx.x, ty = threadIdx.y;   // 32 x 8
#pragma unroll
    for (int i = 0; i < 32; i += 8)
        t[ty + i][tx] = W[(size_t)(k0 + ty + i) * DIM + n0 + tx];
    __syncthreads();
#pragma unroll
    for (int i = 0; i < 32; i += 8) {
        float x = t[tx][ty + i];              // W[k0+tx][n0+ty+i]
        __nv_bfloat16 h = __float2bfloat16(x);
        float r = x - __bfloat162float(h);
        size_t o = (size_t)(n0 + ty + i) * DIM + k0 + tx;
        hi[o] = h;
        lo[o] = __float2bfloat16(r);
    }
}

// ---------------------------------------------------------------------------
// bf16x3 mma.sync GEMM:  C = Ahi@B^T(hi) + Ahi@B^T(lo) + Alo@B^T(hi) + bias
// A: [m][k] K-major bf16 hi/lo.  B: [n][k] K-major bf16 hi/lo (pre-transposed W).
// CTA tile 128x128, 8 warps (2M x 4N), warp tile 64x32, K-chunk 64, 3 stages.
// B is row-major n x k in smem == col-major k x n for the mma -> plain ldmatrix.
// ---------------------------------------------------------------------------
__global__ void __launch_bounds__(256, 1)
gemm_mma(const __nv_bfloat16* __restrict__ Ahi, const __nv_bfloat16* __restrict__ Alo,
         const __nv_bfloat16* __restrict__ Bhi, const __nv_bfloat16* __restrict__ Blo,
         const float* __restrict__ bias, float* __restrict__ C) {
    extern __shared__ __align__(1024) char smem[];
    const int tid  = threadIdx.x;
    const int wid  = tid >> 5;
    const int lane = tid & 31;
    const int row0 = blockIdx.y * GM;
    const int col0 = blockIdx.x * GN;
    const uint32_t sb = smem_u32(smem);

    const int wm = wid >> 2;           // 0..1
    const int wn = wid & 3;            // 0..3
    const int m_base = wm * 64;
    const int n_base = wn * 32;

    // ldmatrix lane address components
    // A (x4): lanes 0-7 rows0-7 k0-7 | 8-15 rows8-15 k0-7 | 16-23 rows0-7 k8-15 | 24-31 rows8-15 k8-15
    const int a_row_in = lane & 15;
    const int a_kseg   = (lane >> 4) * 16;
    // B (x4, plain): lanes 0-7 n0-7 k0-7 | 8-15 n0-7 k8-15 | 16-23 n8-15 k0-7 | 24-31 n8-15 k8-15
    const int b_row_in = (lane & 7) + ((lane >> 4) & 1) * 8;
    const int b_kseg   = ((lane >> 3) & 1) * 16;

    float acc[4][4][4];
#pragma unroll
    for (int i = 0; i < 4; i++)
#pragma unroll
        for (int j = 0; j < 4; j++)
#pragma unroll
            for (int e = 0; e < 4; e++) acc[i][j][e] = 0.0f;

    // --- chunk loader: 64 k-elems (128B/row) for A(128) and B(128), hi+lo ---
    auto issue = [&](int c) {
        const uint32_t st = sb + (uint32_t)(c % NSTAGE) * STAGE_BYTES;
        const int k0 = c * GKC;
#pragma unroll
        for (int i = 0; i < 4; i++) {
            int seg = tid + i * 256;
            int r  = seg >> 3;         // row 0..127 (m for A, n for B)
            int s8 = seg & 7;          // 16B segment within row
            uint32_t d = SWZ(r * 128 + s8 * 16);
            size_t ga = (size_t)(row0 + r) * DIM + k0 + s8 * 8;
            size_t gb = (size_t)(col0 + r) * DIM + k0 + s8 * 8;
            cp16(st + RA_HI + d, Ahi + ga);
            cp16(st + RA_LO + d, Alo + ga);
            cp16(st + RB_HI + d, Bhi + gb);
            cp16(st + RB_LO + d, Blo + gb);
        }
        cp_commit();
    };

    issue(0); issue(1); issue(2);

    for (int c = 0; c < NCHUNK; c++) {
        cp_wait<2>();
        __syncthreads();
        const uint32_t st = sb + (uint32_t)(c % NSTAGE) * STAGE_BYTES;

#pragma unroll
        for (int ks = 0; ks < 4; ks++) {
            const int kb = ks * 32;    // byte offset of k16 step within 128B row

            uint32_t ahi[4][4], alo[4][4];
#pragma unroll
            for (int mi = 0; mi < 4; mi++) {
                uint32_t off = SWZ((m_base + mi * 16 + a_row_in) * 128 + kb + a_kseg);
                ldsm_x4(ahi[mi], st + RA_HI + off);
                ldsm_x4(alo[mi], st + RA_LO + off);
            }
            uint32_t bhi[2][4], blo[2][4];
#pragma unroll
            for (int j2 = 0; j2 < 2; j2++) {
                uint32_t off = SWZ((n_base + j2 * 16 + b_row_in) * 128 + kb + b_kseg);
                ldsm_x4(bhi[j2], st + RB_HI + off);
                ldsm_x4(blo[j2], st + RB_LO + off);
            }
#pragma unroll
            for (int mi = 0; mi < 4; mi++) {
#pragma unroll
                for (int j2 = 0; j2 < 2; j2++) {
#pragma unroll
                    for (int h = 0; h < 2; h++) {
                        float* d = acc[mi][j2 * 2 + h];
                        uint32_t h0 = bhi[j2][h * 2], h1 = bhi[j2][h * 2 + 1];
                        mma16816(d, ahi[mi], h0, h1);
                        mma16816(d, ahi[mi], blo[j2][h * 2], blo[j2][h * 2 + 1]);
                        mma16816(d, alo[mi], h0, h1);
                    }
                }
            }
        }
        __syncthreads();
        if (c + NSTAGE < NCHUNK) issue(c + NSTAGE);
    }

    // Epilogue: add bias, store fp32
    const int rw = row0 + m_base;
    const int cw = col0 + n_base;
#pragma unroll
    for (int nj = 0; nj < 4; nj++) {
        int n = cw + nj * 8 + (lane & 3) * 2;
        float bx = __ldg(&bias[n]);
        float by = __ldg(&bias[n + 1]);
#pragma unroll
        for (int mi = 0; mi < 4; mi++) {
            int r = rw + mi * 16 + (lane >> 2);
            float2 v0 = make_float2(acc[mi][nj][0] + bx, acc[mi][nj][1] + by);
            float2 v1 = make_float2(acc[mi][nj][2] + bx, acc[mi][nj][3] + by);
            *(float2*)(C + (size_t)r * DIM + n)       = v0;
            *(float2*)(C + (size_t)(r + 8) * DIM + n) = v1;
        }
    }
}

// ---------------------------------------------------------------------------
// Per-token attention: RoPE(q,k) -> 16x16 scores -> softmax -> ctx.
// Writes scrambled ctx DIRECTLY as bf16 hi/lo for the O projection.
// Scramble: ctx[b,s,h,e] -> row h*128 + s/16, col (s%16)*64 + e
// ---------------------------------------------------------------------------
__global__ __launch_bounds__(256)
void attn_kernel(float* __restrict__ attn_out, int write_attn) {
    __shared__ float q[DIM], k[DIM], v[DIM], qr[DIM], kr[DIM];
    __shared__ float sc[HEADS * HEADS];

    int t   = blockIdx.x;
    int b   = t >> 11;
    int s   = t & (SEQ - 1);
    int tid = threadIdx.x;

    const float* qg = g_q + (size_t)t * DIM;
    const float* kg = g_k + (size_t)t * DIM;
    const float* vg = g_v + (size_t)t * DIM;

    for (int d = tid; d < DIM; d += 256) {
        q[d] = qg[d]; k[d] = kg[d]; v[d] = vg[d];
    }
    __syncthreads();

    for (int d = tid; d < DIM; d += 256) {
        int j = d & (HALF - 1);
        float c  = g_cos[s * HALF + j];
        float sn = g_sin[s * HALF + j];
        float rq = (d < HALF) ? -q[d + HALF] : q[d - HALF];
        float rk = (d < HALF) ? -k[d + HALF] : k[d - HALF];
        qr[d] = q[d] * c + rq * sn;
        kr[d] = k[d] * c + rk * sn;
    }
    __syncthreads();

    {
        int i = tid >> 4, j = tid & 15;
        float sum = 0.0f;
        const float* qp = &qr[i * HD];
        const float* kp = &kr[j * HD];
#pragma unroll
        for (int e = 0; e < HD; e++) sum += qp[e] * kp[e];
        sc[tid] = sum * 0.125f;
    }
    __syncthreads();

    if (tid < HEADS) {
        float m = -1e30f;
#pragma unroll
        for (int j = 0; j < HEADS; j++) m = fmaxf(m, sc[tid * HEADS + j]);
        float ev[HEADS];
        float ssum = 0.0f;
#pragma unroll
        for (int j = 0; j < HEADS; j++) {
            ev[j] = expf(sc[tid * HEADS + j] - m);
            ssum += ev[j];
        }
        float inv = 1.0f / ssum;
#pragma unroll
        for (int j = 0; j < HEADS; j++) sc[tid * HEADS + j] = ev[j] * inv;
    }
    __syncthreads();

    if (write_attn) {
        attn_out[(size_t)t * 256 + tid] = sc[tid];
    }

    for (int idx = tid; idx < DIM; idx += 256) {
        int i = idx >> 6;
        int e = idx & (HD - 1);
        float sum = 0.0f;
#pragma unroll
        for (int j = 0; j < HEADS; j++) sum += sc[i * HEADS + j] * v[j * HD + e];
        int r = i * (SEQ / HEADS) + (s >> 4);
        int c = ((s & 15) << 6) | e;
        size_t off = (size_t)b * SEQ * DIM + (size_t)r * DIM + c;
        __nv_bfloat16 h = __float2bfloat16(sum);
        g_xx_hi[off] = h;
        g_xx_lo[off] = __float2bfloat16(sum - __bfloat162float(h));
    }
}

// ---------------------------------------------------------------------------
// Host launcher
// ---------------------------------------------------------------------------
extern "C" void kernel_launch(void* const* d_in, const int* in_sizes, int n_in,
                              void* d_out, int out_size) {
    const float* inputs  = (const float*)d_in[0];
    const float* context = (const float*)d_in[1];
    const float* Wq = (const float*)d_in[2];
    const float* bq = (const float*)d_in[3];
    const float* Wk = (const float*)d_in[4];
    const float* bk = (const float*)d_in[5];
    const float* Wv = (const float*)d_in[6];
    const float* bv = (const float*)d_in[7];
    const float* Wo = (const float*)d_in[8];
    const float* bo = (const float*)d_in[9];
    float* out = (float*)d_out;

    cudaFuncSetAttribute(gemm_mma, cudaFuncAttributeMaxDynamicSharedMemorySize,
                         SMEM_TOTAL);

    float *pq, *pk, *pv;
    cudaGetSymbolAddress((void**)&pq, g_q);
    cudaGetSymbolAddress((void**)&pk, g_k);
    cudaGetSymbolAddress((void**)&pv, g_v);

    __nv_bfloat16 *in_hi, *in_lo, *cx_hi, *cx_lo, *xx_hi, *xx_lo;
    __nv_bfloat16 *wq_hi, *wq_lo, *wk_hi, *wk_lo, *wv_hi, *wv_lo, *wo_hi, *wo_lo;
    cudaGetSymbolAddress((void**)&in_hi, g_in_hi);
    cudaGetSymbolAddress((void**)&in_lo, g_in_lo);
    cudaGetSymbolAddress((void**)&cx_hi, g_cx_hi);
    cudaGetSymbolAddress((void**)&cx_lo, g_cx_lo);
    cudaGetSymbolAddress((void**)&xx_hi, g_xx_hi);
    cudaGetSymbolAddress((void**)&xx_lo, g_xx_lo);
    cudaGetSymbolAddress((void**)&wq_hi, g_wq_hi);
    cudaGetSymbolAddress((void**)&wq_lo, g_wq_lo);
    cudaGetSymbolAddress((void**)&wk_hi, g_wk_hi);
    cudaGetSymbolAddress((void**)&wk_lo, g_wk_lo);
    cudaGetSymbolAddress((void**)&wv_hi, g_wv_hi);
    cudaGetSymbolAddress((void**)&wv_lo, g_wv_lo);
    cudaGetSymbolAddress((void**)&wo_hi, g_wo_hi);
    cudaGetSymbolAddress((void**)&wo_lo, g_wo_lo);

    const int out_elems  = MTOK * DIM;
    const int attn_elems = MTOK * HEADS * HEADS;
    int write_attn = (out_size >= out_elems + attn_elems) ? 1 : 0;
    float* attn_out = out + out_elems;

    // RoPE tables
    rope_inv_kernel<<<1, 512>>>();
    rope_tab_kernel<<<(SEQ * HALF) / 256, 256>>>();

    // Weight transpose + split
    dim3 wgrid(32, 32), wblk(32, 8);
    convert_w_kernel<<<wgrid, wblk>>>(Wq, wq_hi, wq_lo);
    convert_w_kernel<<<wgrid, wblk>>>(Wk, wk_hi, wk_lo);
    convert_w_kernel<<<wgrid, wblk>>>(Wv, wv_hi, wv_lo);
    convert_w_kernel<<<wgrid, wblk>>>(Wo, wo_hi, wo_lo);

    // Activation splits
    convert_act_kernel<<<(MTOK * DIM) / 1024, 256>>>(inputs,  in_hi, in_lo);
    convert_act_kernel<<<(MTOK * DIM) / 1024, 256>>>(context, cx_hi, cx_lo);

    // Q/K/V projections (tensor cores via mma.sync)
    dim3 ggrid(DIM / GN, MTOK / GM);   // (8, 32) = 256 CTAs
    gemm_mma<<<ggrid, 256, SMEM_TOTAL>>>(in_hi, in_lo, wq_hi, wq_lo, bq, pq);
    gemm_mma<<<ggrid, 256, SMEM_TOTAL>>>(cx_hi, cx_lo, wk_hi, wk_lo, bk, pk);
    gemm_mma<<<ggrid, 256, SMEM_TOTAL>>>(cx_hi, cx_lo, wv_hi, wv_lo, bv, pv);

    // RoPE + per-token head attention + scramble (writes bf16 hi/lo directly)
    attn_kernel<<<MTOK, 256>>>(attn_out, write_attn);

    // Output projection
    gemm_mma<<<ggrid, 256, SMEM_TOTAL>>>(xx_hi, xx_lo, wo_hi, wo_lo, bo, out);
}